// round 16
// baseline (speedup 1.0000x reference)
#include <cuda_runtime.h>
#include <cuda_fp16.h>
#include <cstdint>
#include <math.h>

// ---------------------------------------------------------------------------
// FNetBlock: out = L * X * R^T per 256x256 slice (1024 slices), where
// L = M(pi3)*M(pi1), R = M(pi2)*M(pi0),
// M(p)[k][j] = 2*cos(k*(PI*(2j+1) + s_j*(p-PI))/512), s_j = +1 even j, -1 odd j.
// pi_i are Monte-Carlo estimates via JAX threefry2x32 reproduced exactly.
//
// FUSED GEMMs via mma.sync m16n8k16 fp16, one CTA per (slice, n-half):
//   Phase 1: T'[n][m] = sum_k R[n,k] X[m,k]  (n in this CTA's 128-half)
//            -> fp16 plane in SMEM (no gmem round-trip)
//   Phase 2: out[i][n] = sum_m L[i,m] T'[n,m], B read directly from SMEM T'.
// 2 CTAs/SM for cross-CTA bubble overlap.
// ---------------------------------------------------------------------------

__device__ int     g_counts[4];
__device__ float   g_M[4][65536];
__device__ __half  g_Lh[65536];
__device__ __half  g_Rh[65536];

// ---------------- Threefry-2x32, 20 rounds (JAX-compatible) ----------------
// rotl via mul.wide.u32 (fma pipe) + single LOP3 (a|b)^c (alu pipe).
__device__ __forceinline__ void tf2x32(uint32_t k0, uint32_t k1,
                                       uint32_t x0, uint32_t x1,
                                       uint32_t& o0, uint32_t& o1) {
    uint32_t k2 = k0 ^ k1 ^ 0x1BD11BDAu;
#define TFR(r) { x0 += x1; \
    asm("{\n\t.reg .u64 w;\n\t.reg .u32 lo, hi;\n\t" \
        "mul.wide.u32 w, %0, %1;\n\t" \
        "mov.b64 {lo, hi}, w;\n\t" \
        "lop3.b32 %0, lo, hi, %2, 0x56;\n\t}" \
        : "+r"(x1) : "r"(1u << (r)), "r"(x0)); }
    x0 += k0; x1 += k1;
    TFR(13) TFR(15) TFR(26) TFR(6)
    x0 += k1; x1 += k2 + 1u;
    TFR(17) TFR(29) TFR(16) TFR(24)
    x0 += k2; x1 += k0 + 2u;
    TFR(13) TFR(15) TFR(26) TFR(6)
    x0 += k0; x1 += k1 + 3u;
    TFR(17) TFR(29) TFR(16) TFR(24)
    x0 += k1; x1 += k2 + 4u;
    TFR(13) TFR(15) TFR(26) TFR(6)
    x0 += k2; x1 += k0 + 5u;
#undef TFR
    o0 = x0; o1 = x1;
}

__global__ void zero_counts_kernel() {
    if (threadIdx.x < 4) g_counts[threadIdx.x] = 0;
}

#define PI_ITER 8
#define PI_TPB  256
#define PI_BPP  4096  // (2^23 pairs) / (256 * 8)

__global__ __launch_bounds__(PI_TPB) void pi_kernel() {
    int p   = blockIdx.x >> 12;
    int blk = blockIdx.x & (PI_BPP - 1);

    uint32_t k0, k1;                 // fold_in(key(42), p)
    tf2x32(0u, 42u, 0u, (uint32_t)p, k0, k1);

    int cnt = 0;
#pragma unroll 2
    for (int it = 0; it < PI_ITER; it++) {
        uint32_t t  = (uint32_t)blk * (PI_TPB * PI_ITER) + it * PI_TPB + threadIdx.x;
        uint32_t c0 = 2u * t, c1 = 2u * t + 1u;
        uint32_t a0, a1, b0, b1;
        tf2x32(k0, k1, c0, c0 + 16777216u, a0, a1);
        tf2x32(k0, k1, c1, c1 + 16777216u, b0, b1);
        float ua0 = __uint_as_float((a0 >> 9) | 0x3f800000u) - 1.0f;
        float ub0 = __uint_as_float((b0 >> 9) | 0x3f800000u) - 1.0f;
        float ua1 = __uint_as_float((a1 >> 9) | 0x3f800000u) - 1.0f;
        float ub1 = __uint_as_float((b1 >> 9) | 0x3f800000u) - 1.0f;
        cnt += (ua0 * ua0 + ub0 * ub0 < 1.0f) ? 1 : 0;
        cnt += (ua1 * ua1 + ub1 * ub1 < 1.0f) ? 1 : 0;
    }
    for (int off = 16; off; off >>= 1)
        cnt += __shfl_down_sync(0xffffffffu, cnt, off);
    __shared__ int ws[PI_TPB / 32];
    if ((threadIdx.x & 31) == 0) ws[threadIdx.x >> 5] = cnt;
    __syncthreads();
    if (threadIdx.x == 0) {
        int s = 0;
#pragma unroll
        for (int i = 0; i < PI_TPB / 32; i++) s += ws[i];
        atomicAdd(&g_counts[p], s);
    }
}

// ---------------- Build the 4 effective DCT matrices -----------------------
// Exact-double range reduction + fp32 cosf (error ~1e-7, cheap on fp64 pipe).
__global__ void build_M_kernel() {
    int p = blockIdx.y;
    int k = blockIdx.x;
    int j = threadIdx.x;
    float  pv    = 4.0f * (float)g_counts[p] / 16777216.0f;
    double delta = (double)pv - M_PI;
    double sgn   = (j & 1) ? -1.0 : 1.0;
    double base  = (M_PI * (double)(2 * j + 1) + sgn * delta) * (1.0 / 512.0);
    double t     = (double)k * base * (1.0 / (2.0 * M_PI));
    double r     = t - rint(t);            // [-0.5, 0.5], exact reduction
    float  ang   = (float)(r * (2.0 * M_PI));
    g_M[p][k * 256 + j] = 2.0f * cosf(ang);
}

// L = M3*M1 ; R = M2*M0, written as single fp16 planes, natural row-major
__global__ void compose_kernel() {
    int j = blockIdx.x * 16 + threadIdx.x;
    int i = blockIdx.y * 16 + threadIdx.y;
    float s = 0.f;
    if (blockIdx.z == 0) {
#pragma unroll 8
        for (int t = 0; t < 256; t++)
            s += g_M[3][i * 256 + t] * g_M[1][t * 256 + j];
        g_Lh[i * 256 + j] = __float2half_rn(s);
    } else {
#pragma unroll 8
        for (int t = 0; t < 256; t++)
            s += g_M[2][i * 256 + t] * g_M[0][t * 256 + j];
        g_Rh[i * 256 + j] = __float2half_rn(s);
    }
}

// ---------------- HMMA GEMM helpers ----------------------------------------
__device__ __forceinline__ uint32_t smem_u32(const void* p) {
    uint32_t a;
    asm("{ .reg .u64 t; cvta.to.shared.u64 t, %1; cvt.u32.u64 %0, t; }"
        : "=r"(a) : "l"(p));
    return a;
}

#define LDSM4(R, A) \
    asm volatile("ldmatrix.sync.aligned.m8n8.x4.shared.b16 {%0,%1,%2,%3}, [%4];" \
                 : "=r"((R)[0]), "=r"((R)[1]), "=r"((R)[2]), "=r"((R)[3]) : "r"(A))

#define MMA(D, A, B0, B1) \
    asm volatile("mma.sync.aligned.m16n8k16.row.col.f32.f16.f16.f32 " \
                 "{%0,%1,%2,%3},{%4,%5,%6,%7},{%8,%9},{%0,%1,%2,%3};" \
                 : "+f"((D)[0]), "+f"((D)[1]), "+f"((D)[2]), "+f"((D)[3]) \
                 : "r"((A)[0]), "r"((A)[1]), "r"((A)[2]), "r"((A)[3]), \
                   "r"(B0), "r"(B1))

#define CP_ASYNC16(dst, src) \
    asm volatile("cp.async.ca.shared.global [%0], [%1], 16;" :: "r"(dst), "l"(src))
#define CP_COMMIT() asm volatile("cp.async.commit_group;" ::: "memory")
#define CP_WAIT0()  asm volatile("cp.async.wait_group 0;" ::: "memory")

__device__ __forceinline__ uint32_t packh2(float x, float y) {
    __half hx = __float2half_rn(x), hy = __float2half_rn(y);
    return (uint32_t)__half_as_ushort(hx) | ((uint32_t)__half_as_ushort(hy) << 16);
}

// smem layout (bytes):
//   T' half-plane: 128 n-rows x 512B (256 fp16 m) + 16 pad = stride 528
//                  @ 0, size 67584
//   A stream: [2 bufs][128 rows * 80B]  @ 67584 (20480)
//   B stream: [2 bufs][128 rows * 80B]  @ 88064 (20480)   (phase 1 X only)
static const int TP_ROW     = 528;
static const int OFF_SA     = 67584;
static const int SA_PLANE   = 128 * 80;      // 10240
static const int OFF_SB     = OFF_SA + 2 * SA_PLANE;  // 88064
static const int SB_PLANE   = 128 * 80;      // 10240
static const int SMEM_BYTES = OFF_SB + 2 * SB_PLANE;  // 108544

__global__ __launch_bounds__(256, 2) void fused_kernel(
    const float* __restrict__ X, float* __restrict__ Out) {
    extern __shared__ char smem[];
    uint32_t sbase = smem_u32(smem);
    int tid  = threadIdx.x;
    int warp = tid >> 5, lane = tid & 31;
    int wm = warp & 3, wn = warp >> 2;       // 4 x 2 warp grid, warptile 32x64
    int b    = blockIdx.x >> 1;
    int nh   = blockIdx.x & 1;               // n-half of this CTA

    int pr = tid >> 1, pg = tid & 1;         // 128-row staging

    const float* Xs = X + (size_t)b * 65536;

    float acc[2][8][4];
    float4 pf[4];
    uint32_t hv[8];

    // one k16 step: LDSM A(2, stride 80) + B(4, stride bStride), 16 MMAs
    auto mma_k16 = [&](uint32_t aAddr, uint32_t bAddr, int bStride) {
        uint32_t ah[2][4];
        LDSM4(ah[0], aAddr);
        LDSM4(ah[1], aAddr + 16 * 80);
#pragma unroll
        for (int h = 0; h < 2; h++) {
            uint32_t bf0[4], bf1[4];
            LDSM4(bf0, bAddr + (2 * h) * 16 * bStride);
            LDSM4(bf1, bAddr + (2 * h + 1) * 16 * bStride);
#pragma unroll
            for (int ms = 0; ms < 2; ms++)
#pragma unroll
                for (int j = 0; j < 4; j++) {
                    int nt = h * 4 + j;
                    int s = j & 1;
                    const uint32_t* BF = (j >> 1) ? bf1 : bf0;
                    MMA(acc[ms][nt], ah[ms], BF[s], BF[s + 2]);
                }
        }
    };

    uint32_t aBase = sbase + OFF_SA + (uint32_t)((wm * 32 + (lane & 15)) * 80 + (lane >> 4) * 16);
    uint32_t dstA  = sbase + OFF_SA + (uint32_t)(pr * 80 + pg * 32);

    // =============== PHASE 1: T'[n-half] = R_half * X^T (into smem) ========
    {
        uint32_t bBase = sbase + OFF_SB + (uint32_t)((wn * 64 + (lane & 15)) * 80 + (lane >> 4) * 16);
        const __half* Rg = g_Rh + (size_t)(nh * 128 + pr) * 256 + pg * 16;
        uint32_t dstB = sbase + OFF_SB + (uint32_t)(pr * 80 + pg * 32);

        auto fillA = [&](int buf, int kc) {
            uint32_t da = dstA + buf * SA_PLANE;
            CP_ASYNC16(da,      Rg + kc * 32);
            CP_ASYNC16(da + 16, Rg + kc * 32 + 8);
        };

#pragma unroll 1
        for (int mt2 = 0; mt2 < 2; mt2++) {
            const float* Bx = Xs + (size_t)(mt2 * 128 + pr) * 256 + pg * 16;
            auto loadB = [&](int kc) {
#pragma unroll
                for (int q = 0; q < 4; q++)
                    pf[q] = *(const float4*)(Bx + kc * 32 + q * 4);
            };
            auto storeB = [&](int buf) {
#pragma unroll
                for (int q = 0; q < 4; q++) {
                    hv[2 * q]     = packh2(pf[q].x, pf[q].y);
                    hv[2 * q + 1] = packh2(pf[q].z, pf[q].w);
                }
                uint32_t db = (dstB - sbase) + buf * SB_PLANE;
                *(uint4*)(smem + db)      = make_uint4(hv[0], hv[1], hv[2], hv[3]);
                *(uint4*)(smem + db + 16) = make_uint4(hv[4], hv[5], hv[6], hv[7]);
            };

            fillA(0, 0); CP_COMMIT();
            loadB(0); storeB(0);
            CP_WAIT0();
            __syncthreads();

#pragma unroll
            for (int i = 0; i < 2; i++)
#pragma unroll
                for (int j = 0; j < 8; j++)
#pragma unroll
                    for (int q = 0; q < 4; q++) acc[i][j][q] = 0.f;

#pragma unroll 1
            for (int kc = 0; kc < 8; kc++) {
                int buf = kc & 1;
                if (kc < 7) {
                    fillA(buf ^ 1, kc + 1); CP_COMMIT();
                    loadB(kc + 1);
                }
                mma_k16(aBase + buf * SA_PLANE,      bBase + buf * SB_PLANE,      80);
                mma_k16(aBase + buf * SA_PLANE + 32, bBase + buf * SB_PLANE + 32, 80);
                if (kc < 7) {
                    storeB(buf ^ 1);
                    CP_WAIT0();
                }
                __syncthreads();
            }

            // epilogue -> smem T' half-plane (fp16), rows n 0..127
            int r0 = wm * 32 + (lane >> 2);
            int cc = wn * 64 + (lane & 3) * 2;
#pragma unroll
            for (int ms = 0; ms < 2; ms++)
#pragma unroll
                for (int nt = 0; nt < 8; nt++) {
                    int nrow = r0 + ms * 16;
                    int mcol = mt2 * 128 + cc + nt * 8;
                    float* a = acc[ms][nt];
                    *(uint32_t*)(smem + nrow * TP_ROW + mcol * 2)       = packh2(a[0], a[1]);
                    *(uint32_t*)(smem + (nrow + 8) * TP_ROW + mcol * 2) = packh2(a[2], a[3]);
                }
        }
    }
    __syncthreads();   // all T' writes visible before phase 2 reads

    // =============== PHASE 2: out[:, n-half] = L x T' (B from smem) ========
    {
        uint32_t bT = sbase + (uint32_t)((wn * 64 + (lane & 15)) * TP_ROW + (lane >> 4) * 16);

#pragma unroll 1
        for (int it2 = 0; it2 < 2; it2++) {
            const __half* Lg = g_Lh + (size_t)(it2 * 128 + pr) * 256 + pg * 16;
            auto fillA2 = [&](int buf, int kc) {
                uint32_t da = dstA + buf * SA_PLANE;
                CP_ASYNC16(da,      Lg + kc * 32);
                CP_ASYNC16(da + 16, Lg + kc * 32 + 8);
            };

            fillA2(0, 0); CP_COMMIT(); CP_WAIT0();
            __syncthreads();

#pragma unroll
            for (int i = 0; i < 2; i++)
#pragma unroll
                for (int j = 0; j < 8; j++)
#pragma unroll
                    for (int q = 0; q < 4; q++) acc[i][j][q] = 0.f;

#pragma unroll 1
            for (int kc = 0; kc < 8; kc++) {
                int buf = kc & 1;
                if (kc < 7) { fillA2(buf ^ 1, kc + 1); CP_COMMIT(); }
                mma_k16(aBase + buf * SA_PLANE,      bT + (kc * 2) * 32,     TP_ROW);
                mma_k16(aBase + buf * SA_PLANE + 32, bT + (kc * 2 + 1) * 32, TP_ROW);
                if (kc < 7) CP_WAIT0();
                __syncthreads();
            }

            // epilogue -> gmem out (fp32), cols nh*128 + ...
            int r0 = wm * 32 + (lane >> 2);
            int cc = wn * 64 + (lane & 3) * 2;
            size_t base = (size_t)b * 65536 + nh * 128;
#pragma unroll
            for (int ms = 0; ms < 2; ms++)
#pragma unroll
                for (int nt = 0; nt < 8; nt++) {
                    int row0 = it2 * 128 + r0 + ms * 16;
                    int col0 = cc + nt * 8;
                    float* a = acc[ms][nt];
                    *(float2*)&Out[base + (size_t)row0 * 256 + col0]       = make_float2(a[0], a[1]);
                    *(float2*)&Out[base + (size_t)(row0 + 8) * 256 + col0] = make_float2(a[2], a[3]);
                }
        }
    }
}

// ---------------------------------------------------------------------------
extern "C" void kernel_launch(void* const* d_in, const int* in_sizes, int n_in,
                              void* d_out, int out_size) {
    const float* x = (const float*)d_in[0];
    if (n_in > 1 && in_sizes[0] == 1) x = (const float*)d_in[1];  // robustness
    float* out = (float*)d_out;

    cudaFuncSetAttribute(fused_kernel, cudaFuncAttributeMaxDynamicSharedMemorySize, SMEM_BYTES);

    zero_counts_kernel<<<1, 32>>>();
    pi_kernel<<<4 * PI_BPP, PI_TPB>>>();
    build_M_kernel<<<dim3(256, 4, 1), 256>>>();
    compose_kernel<<<dim3(16, 16, 2), dim3(16, 16, 1)>>>();

    fused_kernel<<<2048, 256, SMEM_BYTES>>>(x, out);
}